// round 17
// baseline (speedup 1.0000x reference)
#include <cuda_runtime.h>
#include <cuda_bf16.h>
#include <cstdint>

#define BB 2
#define LL 2048
#define DD 1024
#define HH 16
#define DKK 64
#define NP (BB*HH)

// Scratch (__device__ globals — no runtime allocation)
__device__ __nv_bfloat16 g_ah[(size_t)BB * LL * DD];   // input act hi / ctx hi
__device__ __nv_bfloat16 g_al[(size_t)BB * LL * DD];   // input act lo / ctx lo
__device__ __nv_bfloat16 g_bh[(size_t)DD * DD];        // W^T hi
__device__ __nv_bfloat16 g_bl[(size_t)DD * DD];        // W^T lo
__device__ __nv_bfloat16 g_qhb[(size_t)BB * LL * DD];  // Q-proj out bf16
__device__ __nv_bfloat16 g_khb[(size_t)BB * LL * DD];  // K-proj out bf16
__device__ __nv_bfloat16 g_vhh[(size_t)BB * LL * DD];  // V-proj out hi
__device__ __nv_bfloat16 g_vhl[(size_t)BB * LL * DD];  // V-proj out lo

// ---- helpers --------------------------------------------------------------
__device__ __forceinline__ uint32_t smem_u32(const void* p) {
    uint32_t a;
    asm("{ .reg .u64 t; cvta.to.shared.u64 t, %1; cvt.u32.u64 %0, t; }"
        : "=r"(a) : "l"(p));
    return a;
}
__device__ __forceinline__ void ldm_x4(uint32_t* r, uint32_t addr) {
    asm volatile("ldmatrix.sync.aligned.m8n8.x4.shared.b16 {%0,%1,%2,%3}, [%4];"
                 : "=r"(r[0]), "=r"(r[1]), "=r"(r[2]), "=r"(r[3]) : "r"(addr));
}
__device__ __forceinline__ void ldm_x4_t(uint32_t* r, uint32_t addr) {
    asm volatile("ldmatrix.sync.aligned.m8n8.x4.trans.shared.b16 {%0,%1,%2,%3}, [%4];"
                 : "=r"(r[0]), "=r"(r[1]), "=r"(r[2]), "=r"(r[3]) : "r"(addr));
}
__device__ __forceinline__ void mma_bf16(float* c, const uint32_t* a,
                                         const uint32_t* b) {
    asm volatile(
        "mma.sync.aligned.m16n8k16.row.col.f32.bf16.bf16.f32 "
        "{%0,%1,%2,%3}, {%4,%5,%6,%7}, {%8,%9}, {%0,%1,%2,%3};"
        : "+f"(c[0]), "+f"(c[1]), "+f"(c[2]), "+f"(c[3])
        : "r"(a[0]), "r"(a[1]), "r"(a[2]), "r"(a[3]), "r"(b[0]), "r"(b[1]));
}
__device__ __forceinline__ void split2(float x, float y, uint32_t& hi, uint32_t& lo) {
    __nv_bfloat16 hx = __float2bfloat16(x);
    __nv_bfloat16 hy = __float2bfloat16(y);
    float lx = x - __bfloat162float(hx);
    float ly = y - __bfloat162float(hy);
    __nv_bfloat162 hp; hp.x = hx; hp.y = hy;
    __nv_bfloat162 lp = __floats2bfloat162_rn(lx, ly);
    hi = *(uint32_t*)&hp;
    lo = *(uint32_t*)&lp;
}
__device__ __forceinline__ uint32_t bfpack(float x, float y) {
    __nv_bfloat162 t = __floats2bfloat162_rn(x, y);
    return *(uint32_t*)&t;
}
__device__ __forceinline__ void cpasync16(uint32_t sdst, const void* gsrc) {
    asm volatile("cp.async.ca.shared.global [%0], [%1], 16;"
                 :: "r"(sdst), "l"(gsrc));
}

// ---------------------------------------------------------------------------
__global__ __launch_bounds__(256) void conv_a_kernel(
    const float* __restrict__ A, __nv_bfloat16* __restrict__ Ah,
    __nv_bfloat16* __restrict__ Al, int n4)
{
    int i = blockIdx.x * blockDim.x + threadIdx.x;
    if (i >= n4) return;
    float4 v = *(const float4*)(A + (size_t)i * 4);
    uint32_t h01, l01, h23, l23;
    split2(v.x, v.y, h01, l01);
    split2(v.z, v.w, h23, l23);
    uint32_t* ph = (uint32_t*)Ah + (size_t)i * 2;
    uint32_t* pl = (uint32_t*)Al + (size_t)i * 2;
    ph[0] = h01; ph[1] = h23;
    pl[0] = l01; pl[1] = l23;
}
__global__ __launch_bounds__(256) void conv_a_h_kernel(
    const float* __restrict__ A, __nv_bfloat16* __restrict__ Ah, int n4)
{
    int i = blockIdx.x * blockDim.x + threadIdx.x;
    if (i >= n4) return;
    float4 v = *(const float4*)(A + (size_t)i * 4);
    uint32_t* ph = (uint32_t*)Ah + (size_t)i * 2;
    ph[0] = bfpack(v.x, v.y);
    ph[1] = bfpack(v.z, v.w);
}
template<int SPLIT>
__global__ __launch_bounds__(256) void conv_wt_kernel(
    const float* __restrict__ W, __nv_bfloat16* __restrict__ Th,
    __nv_bfloat16* __restrict__ Tl, int K, int N)
{
    __shared__ float ts[32][33];
    int k0 = blockIdx.y * 32;
    int n0 = blockIdx.x * 32;
    int tx = threadIdx.x & 31;
    int ty = threadIdx.x >> 5;
    #pragma unroll
    for (int i = 0; i < 4; ++i) {
        int k = ty + i * 8;
        ts[k][tx] = W[(size_t)(k0 + k) * N + n0 + tx];
    }
    __syncthreads();
    #pragma unroll
    for (int i = 0; i < 4; ++i) {
        int n = ty + i * 8;
        float x = ts[tx][n];
        __nv_bfloat16 h = __float2bfloat16(x);
        Th[(size_t)(n0 + n) * K + k0 + tx] = h;
        if (SPLIT == 3) {
            float l = x - __bfloat162float(h);
            Tl[(size_t)(n0 + n) * K + k0 + tx] = __float2bfloat16(l);
        }
    }
}

// ---------------------------------------------------------------------------
// bf16 HMMA GEMM (unchanged: 3-stage cp.async ring).
// ---------------------------------------------------------------------------
#define GA_H 0
#define GA_L 8192
#define GB_H 16384
#define GB_L 24576
#define GBUF 32768
#define GEMM_SMEM3 (3*GBUF)
#define G1_B 8192
#define G1BUF 16384
#define GEMM_SMEM1 (3*G1BUF)

template<int SPLIT, int OUT>
__global__ __launch_bounds__(256, 2) void gemm_bf16_kernel(
    const __nv_bfloat16* __restrict__ Ah, const __nv_bfloat16* __restrict__ Al,
    const __nv_bfloat16* __restrict__ Bh, const __nv_bfloat16* __restrict__ Bl,
    const float* __restrict__ bias, float* __restrict__ C,
    __nv_bfloat16* __restrict__ Ch, __nv_bfloat16* __restrict__ Cl,
    int M, int N, int K)
{
    extern __shared__ char smem[];
    const uint32_t sbase = smem_u32(smem);
    const int tid  = threadIdx.x;
    const int wid  = tid >> 5;
    const int lane = tid & 31;
    const int m0 = blockIdx.y * 128;
    const int n0 = blockIdx.x * 128;
    const int wm = (wid & 1) * 64;
    const int wn = (wid >> 1) * 32;

    const uint32_t BUFSTRIDE = (SPLIT == 3) ? GBUF : G1BUF;
    const uint32_t OFFB      = (SPLIT == 3) ? GB_H : G1_B;

    float c[4][4][4];
    #pragma unroll
    for (int mt = 0; mt < 4; ++mt)
        #pragma unroll
        for (int no = 0; no < 4; ++no)
            #pragma unroll
            for (int e = 0; e < 4; ++e) c[mt][no][e] = 0.f;

    const int j0 = tid * 2;
    auto issue = [&](int t) {
        uint32_t sb = sbase + (uint32_t)(t % 3) * BUFSTRIDE;
        #pragma unroll
        for (int i = 0; i < 2; ++i) {
            int j = j0 + i;
            int r = j >> 2;
            int cch = j & 3;
            uint32_t sw = (uint32_t)r * 64 + (uint32_t)((cch ^ (r & 3)) << 4);
            size_t ga = (size_t)(m0 + r) * K + t * 32 + cch * 8;
            size_t gb = (size_t)(n0 + r) * K + t * 32 + cch * 8;
            cpasync16(sb + GA_H + sw, Ah + ga);
            cpasync16(sb + OFFB + sw, Bh + gb);
            if (SPLIT == 3) {
                cpasync16(sb + GA_L + sw, Al + ga);
                cpasync16(sb + GB_L + sw, Bl + gb);
            }
        }
        asm volatile("cp.async.commit_group;" ::: "memory");
    };

    const uint32_t a_lrow = (uint32_t)(lane & 15);
    const uint32_t a_cc   = (uint32_t)(lane >> 4);
    const uint32_t b_lrow = (uint32_t)((lane >> 4) * 8 + (lane & 7));
    const uint32_t b_cc   = (uint32_t)((lane >> 3) & 1);

    const int NT = K / 32;
    issue(0);
    issue(1);

    for (int t = 0; t < NT; ++t) {
        if (t + 1 < NT)
            asm volatile("cp.async.wait_group 1;" ::: "memory");
        else
            asm volatile("cp.async.wait_group 0;" ::: "memory");
        __syncthreads();
        if (t + 2 < NT) issue(t + 2);

        const uint32_t bb = sbase + (uint32_t)(t % 3) * BUFSTRIDE;

        #pragma unroll
        for (int ks = 0; ks < 2; ++ks) {
            uint32_t af[4][4];
            #pragma unroll
            for (int mt = 0; mt < 4; ++mt) {
                uint32_t row = (uint32_t)(wm + mt * 16) + a_lrow;
                uint32_t cch = (uint32_t)(ks * 2) + a_cc;
                ldm_x4(af[mt], bb + GA_H + row * 64 + ((cch ^ (row & 3)) << 4));
            }
            uint32_t bh[4][2], bl[4][2];
            #pragma unroll
            for (int half = 0; half < 2; ++half) {
                uint32_t r[4];
                uint32_t nrow = (uint32_t)(wn + half * 16) + b_lrow;
                uint32_t cch = (uint32_t)(ks * 2) + b_cc;
                uint32_t sw = nrow * 64 + ((cch ^ (nrow & 3)) << 4);
                ldm_x4(r, bb + OFFB + sw);
                bh[half * 2][0] = r[0]; bh[half * 2][1] = r[1];
                bh[half * 2 + 1][0] = r[2]; bh[half * 2 + 1][1] = r[3];
                if (SPLIT == 3) {
                    ldm_x4(r, bb + GB_L + sw);
                    bl[half * 2][0] = r[0]; bl[half * 2][1] = r[1];
                    bl[half * 2 + 1][0] = r[2]; bl[half * 2 + 1][1] = r[3];
                }
            }

            #pragma unroll
            for (int mt = 0; mt < 4; ++mt)
                #pragma unroll
                for (int no = 0; no < 4; ++no)
                    mma_bf16(c[mt][no], af[mt], bh[no]);

            if (SPLIT == 3) {
                #pragma unroll
                for (int mt = 0; mt < 4; ++mt)
                    #pragma unroll
                    for (int no = 0; no < 4; ++no)
                        mma_bf16(c[mt][no], af[mt], bl[no]);
                #pragma unroll
                for (int mt = 0; mt < 4; ++mt) {
                    uint32_t row = (uint32_t)(wm + mt * 16) + a_lrow;
                    uint32_t cch = (uint32_t)(ks * 2) + a_cc;
                    ldm_x4(af[mt], bb + GA_L + row * 64 + ((cch ^ (row & 3)) << 4));
                }
                #pragma unroll
                for (int mt = 0; mt < 4; ++mt)
                    #pragma unroll
                    for (int no = 0; no < 4; ++no)
                        mma_bf16(c[mt][no], af[mt], bh[no]);
            }
        }
    }

    const int erow = lane >> 2;
    const int ecol = (lane & 3) * 2;
    #pragma unroll
    for (int mt = 0; mt < 4; ++mt) {
        int r0 = m0 + wm + mt * 16 + erow;
        #pragma unroll
        for (int no = 0; no < 4; ++no) {
            int col = n0 + wn + no * 8 + ecol;
            float2 bv = *(const float2*)(bias + col);
            float o0 = c[mt][no][0] + bv.x;
            float o1 = c[mt][no][1] + bv.y;
            float o2 = c[mt][no][2] + bv.x;
            float o3 = c[mt][no][3] + bv.y;
            if (OUT == 0) {
                float2 o;
                o.x = o0; o.y = o1;
                *(float2*)(C + (size_t)r0 * N + col) = o;
                o.x = o2; o.y = o3;
                *(float2*)(C + (size_t)(r0 + 8) * N + col) = o;
            } else if (OUT == 1) {
                *(uint32_t*)(Ch + (size_t)r0 * N + col) = bfpack(o0, o1);
                *(uint32_t*)(Ch + (size_t)(r0 + 8) * N + col) = bfpack(o2, o3);
            } else {
                uint32_t hi, lo;
                split2(o0, o1, hi, lo);
                *(uint32_t*)(Ch + (size_t)r0 * N + col) = hi;
                *(uint32_t*)(Cl + (size_t)r0 * N + col) = lo;
                split2(o2, o3, hi, lo);
                *(uint32_t*)(Ch + (size_t)(r0 + 8) * N + col) = hi;
                *(uint32_t*)(Cl + (size_t)(r0 + 8) * N + col) = lo;
            }
        }
    }
}

// ---------------------------------------------------------------------------
// Fused attention with S-recompute. Phase-2 ring is now 3-STAGE (the R16 bug
// was issue(t+2) into a 2-stage ring = overwrite of the live buffer).
// ---------------------------------------------------------------------------
#define FQ 0
#define FK 16384
#define FK_STAGE 16384
#define P2_BASE 16384
#define P2_STAGE 49152
#define P2_VH 16384
#define P2_VL 32768
#define FUSED_SMEM (16384 + 3*49152)   // 163840

__global__ __launch_bounds__(256, 1) void attn_fused_kernel(
    const __nv_bfloat16* __restrict__ qhb, const __nv_bfloat16* __restrict__ khb,
    const int* __restrict__ mask,
    const __nv_bfloat16* __restrict__ vhh, const __nv_bfloat16* __restrict__ vhl,
    float* __restrict__ attn,
    __nv_bfloat16* __restrict__ ctx_h, __nv_bfloat16* __restrict__ ctx_l)
{
    extern __shared__ char smem[];
    __shared__ float srow[128];
    const uint32_t sbase = smem_u32(smem);
    const int tid = threadIdx.x;
    const int wid = tid >> 5;
    const int lane = tid & 31;
    const int p = blockIdx.y;
    const int b = p / HH;
    const int h = p % HH;
    const int q0 = blockIdx.x * 128;

    if (tid < 128) srow[tid] = 0.f;

    const __nv_bfloat16* Qg = qhb + (size_t)(b * LL + q0) * DD + h * DKK;
    const __nv_bfloat16* Kg0 = khb + (size_t)b * LL * DD + h * DKK;
    const __nv_bfloat16* Vh0 = vhh + (size_t)b * LL * DD + h * DKK;
    const __nv_bfloat16* Vl0 = vhl + (size_t)b * LL * DD + h * DKK;

    // Q tile once
    {
        #pragma unroll
        for (int i = 0; i < 4; ++i) {
            int j = tid * 4 + i;
            int r = j >> 3;
            int cch = j & 7;
            uint32_t sw = (uint32_t)r * 128 + (uint32_t)((cch ^ (r & 7)) << 4);
            cpasync16(sbase + FQ + sw, Qg + (size_t)r * DD + cch * 8);
        }
        asm volatile("cp.async.commit_group;" ::: "memory");
    }
    auto issueK1 = [&](int t) {
        uint32_t sb = sbase + FK + (uint32_t)(t % 3) * FK_STAGE;
        const __nv_bfloat16* Kg = Kg0 + (size_t)(t * 128) * DD;
        #pragma unroll
        for (int i = 0; i < 4; ++i) {
            int j = tid * 4 + i;
            int r = j >> 3;
            int cch = j & 7;
            uint32_t sw = (uint32_t)r * 128 + (uint32_t)((cch ^ (r & 7)) << 4);
            cpasync16(sb + sw, Kg + (size_t)r * DD + cch * 8);
        }
        asm volatile("cp.async.commit_group;" ::: "memory");
    };
    issueK1(0);
    issueK1(1);

    const int wm = (wid & 3) * 32;
    const int wk = (wid >> 2) * 64;
    const uint32_t a_lrow = (uint32_t)(lane & 15);
    const uint32_t a_cc   = (uint32_t)(lane >> 4);
    const uint32_t b_lrow = (uint32_t)((lane >> 4) * 8 + (lane & 7));
    const uint32_t b_cc   = (uint32_t)((lane >> 3) & 1);
    const int erow = lane >> 2;
    const int ecol = (lane & 3) * 2;
    const float scale = 1.0f / (float)DD;
    const size_t obase = (size_t)(h * BB + b) * LL * LL;

    const int NKT = LL / 128;  // 16

    auto s_mma = [&](uint32_t kb, float (*cS)[8][4]) {
        #pragma unroll
        for (int ks = 0; ks < 4; ++ks) {
            uint32_t af[2][4];
            #pragma unroll
            for (int mt = 0; mt < 2; ++mt) {
                uint32_t row = (uint32_t)(wm + mt * 16) + a_lrow;
                uint32_t cch = (uint32_t)(ks * 2) + a_cc;
                ldm_x4(af[mt], sbase + FQ + row * 128 + ((cch ^ (row & 7)) << 4));
            }
            uint32_t bf[8][2];
            #pragma unroll
            for (int half = 0; half < 4; ++half) {
                uint32_t r[4];
                uint32_t nrow = (uint32_t)(wk + half * 16) + b_lrow;
                uint32_t cch = (uint32_t)(ks * 2) + b_cc;
                ldm_x4(r, kb + nrow * 128 + ((cch ^ (nrow & 7)) << 4));
                bf[half * 2][0] = r[0]; bf[half * 2][1] = r[1];
                bf[half * 2 + 1][0] = r[2]; bf[half * 2 + 1][1] = r[3];
            }
            #pragma unroll
            for (int mt = 0; mt < 2; ++mt)
                #pragma unroll
                for (int no = 0; no < 8; ++no)
                    mma_bf16(cS[mt][no], af[mt], bf[no]);
        }
    };

    // ---------------- Phase 1: rowsum only ----------------
    for (int kt = 0; kt < NKT; ++kt) {
        if (kt + 1 < NKT)
            asm volatile("cp.async.wait_group 1;" ::: "memory");
        else
            asm volatile("cp.async.wait_group 0;" ::: "memory");
        __syncthreads();
        if (kt + 2 < NKT) issueK1(kt + 2);

        float cS[2][8][4];
        #pragma unroll
        for (int mt = 0; mt < 2; ++mt)
            #pragma unroll
            for (int no = 0; no < 8; ++no)
                #pragma unroll
                for (int e = 0; e < 4; ++e) cS[mt][no][e] = 0.f;

        s_mma(sbase + FK + (uint32_t)(kt % 3) * FK_STAGE, cS);

        const int k0 = kt * 128;
        #pragma unroll
        for (int mt = 0; mt < 2; ++mt) {
            #pragma unroll
            for (int r2 = 0; r2 < 2; ++r2) {
                int row = wm + mt * 16 + erow + r2 * 8;
                int q = q0 + row;
                const int* mbase = mask + ((size_t)b * LL + q) * LL;
                float rsum = 0.f;
                #pragma unroll
                for (int no = 0; no < 8; ++no) {
                    int col = k0 + wk + no * 8 + ecol;
                    int2 m = *(const int2*)(mbase + col);
                    float e0 = m.x ? __expf(cS[mt][no][r2 * 2 + 0] * scale) : 0.f;
                    float e1 = m.y ? __expf(cS[mt][no][r2 * 2 + 1] * scale) : 0.f;
                    rsum += e0 + e1;
                }
                rsum += __shfl_xor_sync(0xffffffffu, rsum, 1);
                rsum += __shfl_xor_sync(0xffffffffu, rsum, 2);
                if ((lane & 3) == 0) atomicAdd(&srow[row], rsum);
            }
        }
    }

    asm volatile("cp.async.wait_group 0;" ::: "memory");
    __syncthreads();   // srow final

    // ---------------- Phase 2: recompute + write + AV (3-stage ring) -------
    auto issue2 = [&](int t) {
        uint32_t sb = sbase + P2_BASE + (uint32_t)(t % 3) * P2_STAGE;
        const __nv_bfloat16* Kg = Kg0 + (size_t)(t * 128) * DD;
        const __nv_bfloat16* Vh = Vh0 + (size_t)(t * 128) * DD;
        const __nv_bfloat16* Vl = Vl0 + (size_t)(t * 128) * DD;
        #pragma unroll
        for (int i = 0; i < 4; ++i) {
            int j = tid * 4 + i;
            int r = j >> 3;
            int cch = j & 7;
            uint32_t sw = (uint32_t)r * 128 + (uint32_t)((cch ^ (r & 7)) << 4);
            size_t g = (size_t)r * DD + cch * 8;
            cpasync16(sb + sw, Kg + g);
            cpasync16(sb + P2_VH + sw, Vh + g);
            cpasync16(sb + P2_VL + sw, Vl + g);
        }
        asm volatile("cp.async.commit_group;" ::: "memory");
    };
    issue2(0);
    issue2(1);

    float ctx[2][8][4];
    #pragma unroll
    for (int mt = 0; mt < 2; ++mt)
        #pragma unroll
        for (int no = 0; no < 8; ++no)
            #pragma unroll
            for (int e = 0; e < 4; ++e) ctx[mt][no][e] = 0.f;

    const int vm = lane >> 3;
    const int v_krow_off = (vm & 1) * 8 + (lane & 7);
    const int v_nc_off = (vm >> 1);

    float invs[2][2];
    #pragma unroll
    for (int mt = 0; mt < 2; ++mt)
        #pragma unroll
        for (int r2 = 0; r2 < 2; ++r2)
            invs[mt][r2] = 1.0f / srow[wm + mt * 16 + erow + r2 * 8];

    for (int kt = 0; kt < NKT; ++kt) {
        if (kt + 1 < NKT)
            asm volatile("cp.async.wait_group 1;" ::: "memory");
        else
            asm volatile("cp.async.wait_group 0;" ::: "memory");
        __syncthreads();
        if (kt + 2 < NKT) issue2(kt + 2);

        uint32_t sb = sbase + P2_BASE + (uint32_t)(kt % 3) * P2_STAGE;

        float cS[2][8][4];
        #pragma unroll
        for (int mt = 0; mt < 2; ++mt)
            #pragma unroll
            for (int no = 0; no < 8; ++no)
                #pragma unroll
                for (int e = 0; e < 4; ++e) cS[mt][no][e] = 0.f;

        s_mma(sb, cS);

        const int k0 = kt * 128;
        #pragma unroll
        for (int mt = 0; mt < 2; ++mt) {
            #pragma unroll
            for (int r2 = 0; r2 < 2; ++r2) {
                int row = wm + mt * 16 + erow + r2 * 8;
                int q = q0 + row;
                float inv = invs[mt][r2];
                const int* mbase = mask + ((size_t)b * LL + q) * LL;
                float* orow = attn + obase + (size_t)q * LL;
                #pragma unroll
                for (int no = 0; no < 8; ++no) {
                    int col = k0 + wk + no * 8 + ecol;
                    int2 m = *(const int2*)(mbase + col);
                    float e0 = m.x ? __expf(cS[mt][no][r2 * 2 + 0] * scale) * inv : 0.f;
                    float e1 = m.y ? __expf(cS[mt][no][r2 * 2 + 1] * scale) * inv : 0.f;
                    float2 o; o.x = e0; o.y = e1;
                    *(float2*)(orow + col) = o;
                    cS[mt][no][r2 * 2 + 0] = e0;
                    cS[mt][no][r2 * 2 + 1] = e1;
                }
            }
        }

        #pragma unroll
        for (int t2 = 0; t2 < 4; ++t2) {
            uint32_t vhf[8][2], vlf[8][2];
            #pragma unroll
            for (int ng = 0; ng < 4; ++ng) {
                uint32_t r[4];
                uint32_t k_row = (uint32_t)(wk + t2 * 16 + v_krow_off);
                uint32_t cch = (uint32_t)(2 * ng + v_nc_off);
                uint32_t sw = k_row * 128 + ((cch ^ (k_row & 7)) << 4);
                ldm_x4_t(r, sb + P2_VH + sw);
                vhf[ng * 2][0] = r[0]; vhf[ng * 2][1] = r[1];
                vhf[ng * 2 + 1][0] = r[2]; vhf[ng * 2 + 1][1] = r[3];
                ldm_x4_t(r, sb + P2_VL + sw);
                vlf[ng * 2][0] = r[0]; vlf[ng * 2][1] = r[1];
                vlf[ng * 2 + 1][0] = r[2]; vlf[ng * 2 + 1][1] = r[3];
            }
            #pragma unroll
            for (int mt = 0; mt < 2; ++mt) {
                uint32_t pha[4], pla[4];
                split2(cS[mt][2 * t2][0], cS[mt][2 * t2][1], pha[0], pla[0]);
                split2(cS[mt][2 * t2][2], cS[mt][2 * t2][3], pha[1], pla[1]);
                split2(cS[mt][2 * t2 + 1][0], cS[mt][2 * t2 + 1][1], pha[2], pla[2]);
                split2(cS[mt][2 * t2 + 1][2], cS[mt][2 * t2 + 1][3], pha[3], pla[3]);
                #pragma unroll
                for (int no = 0; no < 8; ++no) {
                    mma_bf16(ctx[mt][no], pha, vhf[no]);
                    mma_bf16(ctx[mt][no], pha, vlf[no]);
                    mma_bf16(ctx[mt][no], pla, vhf[no]);
                }
            }
        }
    }

    // ---------------- ctx cross-warp reduce + store ----------------
    __syncthreads();
    float* sctx = (float*)smem;
    if (wid < 4) {
        #pragma unroll
        for (int mt = 0; mt < 2; ++mt)
            #pragma unroll
            for (int r2 = 0; r2 < 2; ++r2) {
                int row = wm + mt * 16 + erow + r2 * 8;
                #pragma unroll
                for (int no = 0; no < 8; ++no) {
                    int col = no * 8 + ecol;
                    sctx[row * 66 + col]     = ctx[mt][no][r2 * 2 + 0];
                    sctx[row * 66 + col + 1] = ctx[mt][no][r2 * 2 + 1];
                }
            }
    }
    __syncthreads();
    if (wid >= 4) {
        #pragma unroll
        for (int mt = 0; mt < 2; ++mt)
            #pragma unroll
            for (int r2 = 0; r2 < 2; ++r2) {
                int row = wm + mt * 16 + erow + r2 * 8;
                int q = q0 + row;
                size_t gbase = ((size_t)b * LL + q) * DD + h * DKK;
                #pragma unroll
                for (int no = 0; no < 8; ++no) {
                    int col = no * 8 + ecol;
                    float s0 = sctx[row * 66 + col]     + ctx[mt][no][r2 * 2 + 0];
                    float s1 = sctx[row * 66 + col + 1] + ctx[mt][no][r2 * 2 + 1];
                    uint32_t hi, lo;
                    split2(s0, s1, hi, lo);
                    *(uint32_t*)(ctx_h + gbase + col) = hi;
                    *(uint32_t*)(ctx_l + gbase + col) = lo;
                }
            }
    }
}

// ---------------------------------------------------------------------------
extern "C" void kernel_launch(void* const* d_in, const int* in_sizes, int n_in,
                              void* d_out, int out_size)
{
    const float* q    = (const float*)d_in[0];
    const float* k    = (const float*)d_in[1];
    const float* v    = (const float*)d_in[2];
    const int*   mask = (const int*)d_in[3];
    const float* Wq   = (const float*)d_in[4];
    const float* bq   = (const float*)d_in[5];
    const float* Wk   = (const float*)d_in[6];
    const float* bk   = (const float*)d_in[7];
    const float* Wv   = (const float*)d_in[8];
    const float* bv   = (const float*)d_in[9];
    const float* Wo   = (const float*)d_in[10];
    const float* bo   = (const float*)d_in[11];

    float* out  = (float*)d_out;
    float* attn = out + (size_t)BB * LL * DD;

    __nv_bfloat16 *ah, *al, *bh, *bl, *qhb, *khb, *vhh, *vhl;
    cudaGetSymbolAddress((void**)&ah, g_ah);
    cudaGetSymbolAddress((void**)&al, g_al);
    cudaGetSymbolAddress((void**)&bh, g_bh);
    cudaGetSymbolAddress((void**)&bl, g_bl);
    cudaGetSymbolAddress((void**)&qhb, g_qhb);
    cudaGetSymbolAddress((void**)&khb, g_khb);
    cudaGetSymbolAddress((void**)&vhh, g_vhh);
    cudaGetSymbolAddress((void**)&vhl, g_vhl);

    const int M = BB * LL;  // 4096
    const int n4 = M * DD / 4;

    static int smem_set = 0;
    if (!smem_set) {
        cudaFuncSetAttribute(gemm_bf16_kernel<1,1>,
                             cudaFuncAttributeMaxDynamicSharedMemorySize, GEMM_SMEM1);
        cudaFuncSetAttribute(gemm_bf16_kernel<3,2>,
                             cudaFuncAttributeMaxDynamicSharedMemorySize, GEMM_SMEM3);
        cudaFuncSetAttribute(gemm_bf16_kernel<3,0>,
                             cudaFuncAttributeMaxDynamicSharedMemorySize, GEMM_SMEM3);
        cudaFuncSetAttribute(attn_fused_kernel,
                             cudaFuncAttributeMaxDynamicSharedMemorySize, FUSED_SMEM);
        smem_set = 1;
    }

    dim3 gproj(DD / 128, M / 128);
    dim3 gwt(DD / 32, DD / 32);
    const int cga = (n4 + 255) / 256;

    // Q projection -> bf16
    conv_wt_kernel<1><<<gwt, 256>>>(Wq, bh, bl, DD, DD);
    conv_a_h_kernel<<<cga, 256>>>(q, ah, n4);
    gemm_bf16_kernel<1,1><<<gproj, 256, GEMM_SMEM1>>>(ah, al, bh, bl, bq,
                                                      nullptr, qhb, nullptr, M, DD, DD);
    // K projection -> bf16
    conv_wt_kernel<1><<<gwt, 256>>>(Wk, bh, bl, DD, DD);
    conv_a_h_kernel<<<cga, 256>>>(k, ah, n4);
    gemm_bf16_kernel<1,1><<<gproj, 256, GEMM_SMEM1>>>(ah, al, bh, bl, bk,
                                                      nullptr, khb, nullptr, M, DD, DD);
    // V projection -> bf16 hi/lo
    conv_wt_kernel<3><<<gwt, 256>>>(Wv, bh, bl, DD, DD);
    conv_a_kernel<<<cga, 256>>>(v, ah, al, n4);
    gemm_bf16_kernel<3,2><<<gproj, 256, GEMM_SMEM3>>>(ah, al, bh, bl, bv,
                                                      nullptr, vhh, vhl, M, DD, DD);

    // Fused scores + softmax + AV (recompute, 3-stage phase-2 ring)
    dim3 gf(LL / 128, NP);  // (16, 32)
    attn_fused_kernel<<<gf, 256, FUSED_SMEM>>>(qhb, khb, mask, vhh, vhl,
                                               attn, ah, al);

    // Output projection (ctx bf16 hi/lo in ah/al)
    conv_wt_kernel<3><<<gwt, 256>>>(Wo, bh, bl, DD, DD);
    gemm_bf16_kernel<3,0><<<gproj, 256, GEMM_SMEM3>>>(ah, al, bh, bl, bo,
                                                      out, nullptr, nullptr, M, DD, DD);
}